// round 8
// baseline (speedup 1.0000x reference)
#include <cuda_runtime.h>
#include <stdint.h>

#define N_ROWS   131072
#define C_DIM    64
#define K_CODES  4096
#define M_TILE   128
#define THREADS  256
#define APITCH   68            // padded row pitch (floats) -> conflict-free frags
#define PLANE    8704          // 128*APITCH floats per tile-plane
#define DELTA    0.015625f     // screening margin (>> 4x worst-case 3xTF32 err)
#define CAND_CAP 32

// Output layout: [quantized N*C][idx N][residual_quantized N*C][idx_r N]
#define OFF_Q     ((size_t)0)
#define OFF_IDX   ((size_t)N_ROWS * C_DIM)
#define OFF_RQ    ((size_t)N_ROWS * C_DIM + N_ROWS)
#define OFF_IDXR  ((size_t)2 * N_ROWS * C_DIM + N_ROWS)

// Prebuilt GMEM images: tf32-split (-2*codebook), [n][k] pitch-68 per 128-code
// tile, identical byte layout to the SMEM operand so cp.async is linear.
__device__ float g_imgMainHi[32 * PLANE];
__device__ float g_imgMainLo[32 * PLANE];
__device__ float g_imgResHi [32 * PLANE];
__device__ float g_imgResLo [32 * PLANE];
__device__ float g_csq[K_CODES];
__device__ float g_rsq[K_CODES];

// ---- SMEM float-index map ----
#define SA_HI    0
#define SA_LO    PLANE
#define SB_HI(b) (2 * PLANE + (b) * 2 * PLANE)
#define SB_LO(b) (SB_HI(b) + PLANE)
#define SCSQ(b)  (6 * PLANE + (b) * 128)
#define SRI      (6 * PLANE + 256)
#define SMEM_FLOATS (6 * PLANE + 384)   // 52608 floats = 210432 B

__device__ __forceinline__ float tf32r(float v) {
    uint32_t u; asm("cvt.rna.tf32.f32 %0, %1;" : "=r"(u) : "f"(v));
    return __uint_as_float(u);
}

// ---- Prep: split/pad/transpose codebook images + squared norms ----
__global__ void prep_kernel(const float* __restrict__ cb,
                            const float* __restrict__ rcb) {
    int n = blockIdx.x * blockDim.x + threadIdx.x;
    if (n >= K_CODES) return;
    int t = n >> 7, r = n & 127;
    float* dh = g_imgMainHi + t * PLANE + r * APITCH;
    float* dl = g_imgMainLo + t * PLANE + r * APITCH;
    float s = 0.f;
#pragma unroll 8
    for (int c = 0; c < C_DIM; c++) {
        float v = cb[(size_t)n * C_DIM + c];
        s = fmaf(v, v, s);
        float w = -2.0f * v;
        float h = tf32r(w);
        dh[c] = h; dl[c] = tf32r(w - h);
    }
    g_csq[n] = s;
    dh = g_imgResHi + t * PLANE + r * APITCH;
    dl = g_imgResLo + t * PLANE + r * APITCH;
    s = 0.f;
#pragma unroll 8
    for (int c = 0; c < C_DIM; c++) {
        float v = rcb[(size_t)n * C_DIM + c];
        s = fmaf(v, v, s);
        float w = -2.0f * v;
        float h = tf32r(w);
        dh[c] = h; dl[c] = tf32r(w - h);
    }
    g_rsq[n] = s;
}

__device__ __forceinline__ void cpasync16(uint32_t dst, const float* src) {
    asm volatile("cp.async.cg.shared.global [%0], [%1], 16;"
                 :: "r"(dst), "l"(src) : "memory");
}

__device__ __forceinline__ void mma_tf32(float* d,
                                         float a0, float a1, float a2, float a3,
                                         float b0, float b1) {
    asm volatile(
        "mma.sync.aligned.m16n8k8.row.col.f32.tf32.tf32.f32 "
        "{%0,%1,%2,%3}, {%4,%5,%6,%7}, {%8,%9}, {%0,%1,%2,%3};"
        : "+f"(d[0]), "+f"(d[1]), "+f"(d[2]), "+f"(d[3])
        : "r"(__float_as_uint(a0)), "r"(__float_as_uint(a1)),
          "r"(__float_as_uint(a2)), "r"(__float_as_uint(a3)),
          "r"(__float_as_uint(b0)), "r"(__float_as_uint(b1)));
}

// ---- Exact fp32 rescore of one candidate (rare path; L2-hot loads) ----
__device__ __noinline__ float exact_score(const float* __restrict__ xrow,
                                          const float* __restrict__ qrow,
                                          const float* __restrict__ crow,
                                          float csq)
{
    float d0 = 0.f, d1 = 0.f, d2 = 0.f, d3 = 0.f;
#pragma unroll
    for (int j = 0; j < 16; j++) {
        float4 xv = __ldg((const float4*)xrow + j);
        float4 cv = __ldg((const float4*)crow + j);
        if (qrow) {
            float4 qv = __ldg((const float4*)qrow + j);
            xv.x -= qv.x; xv.y -= qv.y; xv.z -= qv.z; xv.w -= qv.w;
        }
        d0 = fmaf(xv.x, cv.x, d0);
        d1 = fmaf(xv.y, cv.y, d1);
        d2 = fmaf(xv.z, cv.z, d2);
        d3 = fmaf(xv.w, cv.w, d3);
    }
    return fmaf(-2.f, (d0 + d1) + (d2 + d3), csq);
}

struct Ctx {
    const float *xl, *xh, *ql, *qh, *cbsrc, *sqsrc;
};

__device__ __forceinline__ void process_cands(const int* cand, int nc, const Ctx& c,
                                              float& bel, int& iel,
                                              float& beh, int& ieh)
{
    for (int i = 0; i < nc; i++) {
        int v = cand[i];
        int code = v >> 1;
        const float* xrow = (v & 1) ? c.xh : c.xl;
        const float* qrow = (v & 1) ? c.qh : c.ql;
        float e = exact_score(xrow, qrow, c.cbsrc + (size_t)code * C_DIM,
                              __ldg(c.sqsrc + code));
        if (v & 1) { if (e < beh) { beh = e; ieh = code; } }
        else       { if (e < bel) { bel = e; iel = code; } }
    }
}

// cp.async one code tile (hi+lo planes + csq) into buffer buf.
__device__ __forceinline__ void copy_tile(int u, int buf, int tid, uint32_t sb) {
    const float* hi = (u < 32 ? g_imgMainHi : g_imgResHi) + (u & 31) * PLANE;
    const float* lo = (u < 32 ? g_imgMainLo : g_imgResLo) + (u & 31) * PLANE;
    uint32_t dhi = sb + SB_HI(buf) * 4;
    uint32_t dlo = sb + SB_LO(buf) * 4;
#pragma unroll
    for (int o = 0; o < 17; o++) {           // 17*256 = 4352 = 2*2176 chunks
        int i = tid + o * 256;
        if (i < 2176) cpasync16(dhi + i * 16, hi + i * 4);
        else          cpasync16(dlo + (i - 2176) * 16, lo + (i - 2176) * 4);
    }
    if (tid < 32) {
        const float* sq = (u < 32 ? g_csq : g_rsq) + (u & 31) * 128;
        cpasync16(sb + SCSQ(buf) * 4 + tid * 16, sq + tid * 4);
    }
    asm volatile("cp.async.commit_group;" ::: "memory");
}

// Build/refresh one A row (tf32 split of x or residual) into the A planes.
__device__ __forceinline__ void build_row(float* smem, int r,
                                          const float* __restrict__ xrow,
                                          const float* __restrict__ qrow) {
    const float4* xp = (const float4*)xrow;
    const float4* qp = (const float4*)qrow;
#pragma unroll
    for (int j = 0; j < 16; j++) {
        float4 v = xp[j];
        if (qrow) { float4 q = qp[j]; v.x -= q.x; v.y -= q.y; v.z -= q.z; v.w -= q.w; }
        float4 h, l;
        h.x = tf32r(v.x); l.x = tf32r(v.x - h.x);
        h.y = tf32r(v.y); l.y = tf32r(v.y - h.y);
        h.z = tf32r(v.z); l.z = tf32r(v.z - h.z);
        h.w = tf32r(v.w); l.w = tf32r(v.w - h.w);
        *(float4*)(smem + SA_HI + r * APITCH + j * 4) = h;
        *(float4*)(smem + SA_LO + r * APITCH + j * 4) = l;
    }
}

// Stage end: quad-reduce exact argmin, gather/emit outputs, rebuild A (stage 0).
__device__ __forceinline__ void finalize_stage(
    int stage, int row0, int tid, int w, int lane,
    float* smem, const float* __restrict__ cbraw, const float* __restrict__ x,
    float* __restrict__ out,
    float& bel, int& iel, float& beh, int& ieh, float& bl, float& bh)
{
    // lanes 4q..4q+3 share rows (w*16+q) and (w*16+q+8): lexicographic reduce
#pragma unroll
    for (int off = 1; off < 4; off <<= 1) {
        float so = __shfl_xor_sync(0xffffffffu, bel, off);
        int   bo = __shfl_xor_sync(0xffffffffu, iel, off);
        if (so < bel || (so == bel && bo < iel)) { bel = so; iel = bo; }
        so = __shfl_xor_sync(0xffffffffu, beh, off);
        bo = __shfl_xor_sync(0xffffffffu, ieh, off);
        if (so < beh || (so == beh && bo < ieh)) { beh = so; ieh = bo; }
    }
    if ((lane & 3) == 0) {
        int r = w * 16 + (lane >> 2);
        ((int*)smem)[SRI + r]     = iel;
        ((int*)smem)[SRI + r + 8] = ieh;
    }
    __syncthreads();
    if (tid < 128) {
        int r = tid;
        int code = ((int*)smem)[SRI + r];
        const float* qrow = cbraw + (size_t)code * C_DIM;
        float* oq = out + (stage ? OFF_RQ : OFF_Q) + (size_t)(row0 + r) * C_DIM;
#pragma unroll
        for (int j = 0; j < 16; j++)
            *(float4*)(oq + j * 4) = ((const float4*)qrow)[j];
        if (stage == 0)
            build_row(smem, r, x + (size_t)(row0 + r) * C_DIM, qrow);
        out[(stage ? OFF_IDXR : OFF_IDX) + row0 + r] = (float)code;
    }
    bel = beh = 3.402823466e38f; iel = ieh = 0;
    bl  = bh  = 3.402823466e38f;
    __syncthreads();
}

__global__ __launch_bounds__(THREADS, 1)
void rq6_kernel(const float* __restrict__ x,
                const float* __restrict__ cb,
                const float* __restrict__ rcb,
                float* __restrict__ out)
{
    extern __shared__ float smem[];
    const uint32_t sb = (uint32_t)__cvta_generic_to_shared(smem);
    const int tid = threadIdx.x, w = tid >> 5, lane = tid & 31;
    const int row0 = blockIdx.x * M_TILE;

    copy_tile(0, 0, tid, sb);
    copy_tile(1, 1, tid, sb);

    if (tid < 128)
        build_row(smem, tid, x + (size_t)(row0 + tid) * C_DIM, (const float*)0);

    float bl = 3.402823466e38f, bh = 3.402823466e38f;     // approx screens
    float bel = 3.402823466e38f, beh = 3.402823466e38f;   // exact bests
    int   iel = 0, ieh = 0;

    const int ra   = w * 16 + (lane >> 2);         // A frag row
    const int ka   = lane & 3;                     // A/B frag k offset
    const int boff = (lane >> 2) * APITCH + ka;    // B frag base
    const float *qrow_l = 0, *qrow_h = 0;          // stage-0 picks (for stage 1)

    for (int tt = 0; tt < 64; tt++) {
        if (tt < 63) asm volatile("cp.async.wait_group 1;" ::: "memory");
        else         asm volatile("cp.async.wait_group 0;" ::: "memory");
        __syncthreads();

        const int buf = tt & 1;
        const int stage = tt >> 5;
        const float* Bh0 = smem + SB_HI(buf) + boff;
        const float* Bl0 = smem + SB_LO(buf) + boff;

        float acc[16][4];
#pragma unroll
        for (int n = 0; n < 16; n++)
#pragma unroll
            for (int j = 0; j < 4; j++) acc[n][j] = 0.f;

#pragma unroll 2
        for (int ks = 0; ks < 8; ks++) {
            const int k0 = ks * 8;
            const float* Ah = smem + SA_HI + ra * APITCH + k0 + ka;
            const float* Al = smem + SA_LO + ra * APITCH + k0 + ka;
            float ah0 = Ah[0], ah2 = Ah[4], ah1 = Ah[8 * APITCH], ah3 = Ah[8 * APITCH + 4];
            float al0 = Al[0], al2 = Al[4], al1 = Al[8 * APITCH], al3 = Al[8 * APITCH + 4];
            const float* bp  = Bh0 + k0;
            const float* blp = Bl0 + k0;
#pragma unroll
            for (int n = 0; n < 16; n++) {
                float b0 = bp[0],  b1 = bp[4];
                float c0 = blp[0], c1 = blp[4];
                mma_tf32(acc[n], ah0, ah1, ah2, ah3, b0, b1);   // hi*hi
                mma_tf32(acc[n], ah0, ah1, ah2, ah3, c0, c1);   // hi*lo
                mma_tf32(acc[n], al0, al1, al2, al3, b0, b1);   // lo*hi
                bp  += 8 * APITCH;
                blp += 8 * APITCH;
            }
        }

        // ---- Epilogue pass 1: approx scores + tile minima ----
        const float* cs = smem + SCSQ(buf);
        const int cbase = (tt & 31) * 128;
        float tl = 3.402823466e38f, th = 3.402823466e38f;
#pragma unroll
        for (int n = 0; n < 16; n++) {
            int lc = n * 8 + ka * 2;
            float2 c2 = *(const float2*)(cs + lc);
            acc[n][0] += c2.x; acc[n][1] += c2.y;
            acc[n][2] += c2.x; acc[n][3] += c2.y;
            tl = fminf(tl, fminf(acc[n][0], acc[n][1]));
            th = fminf(th, fminf(acc[n][2], acc[n][3]));
        }
        bl = fminf(bl, tl);
        bh = fminf(bh, th);
        const float thr_l = bl + DELTA, thr_h = bh + DELTA;

        // ---- Pass 2: collect candidates within margin, exact-rescore them ----
        Ctx ctx;
        ctx.xl = x + (size_t)(row0 + ra) * C_DIM;
        ctx.xh = ctx.xl + 8 * C_DIM;
        ctx.ql = stage ? qrow_l : (const float*)0;
        ctx.qh = stage ? qrow_h : (const float*)0;
        ctx.cbsrc = stage ? rcb : cb;
        ctx.sqsrc = stage ? g_rsq : g_csq;

        int cand[CAND_CAP];
        int nc = 0;
#pragma unroll
        for (int n = 0; n < 16; n++) {
            const int g = cbase + n * 8 + ka * 2;
            if (acc[n][0] < thr_l) {
                if (nc == CAND_CAP) { process_cands(cand, nc, ctx, bel, iel, beh, ieh); nc = 0; }
                cand[nc++] = (g << 1);
            }
            if (acc[n][1] < thr_l) {
                if (nc == CAND_CAP) { process_cands(cand, nc, ctx, bel, iel, beh, ieh); nc = 0; }
                cand[nc++] = ((g + 1) << 1);
            }
            if (acc[n][2] < thr_h) {
                if (nc == CAND_CAP) { process_cands(cand, nc, ctx, bel, iel, beh, ieh); nc = 0; }
                cand[nc++] = (g << 1) | 1;
            }
            if (acc[n][3] < thr_h) {
                if (nc == CAND_CAP) { process_cands(cand, nc, ctx, bel, iel, beh, ieh); nc = 0; }
                cand[nc++] = ((g + 1) << 1) | 1;
            }
        }
        process_cands(cand, nc, ctx, bel, iel, beh, ieh);
        __syncthreads();

        if (tt == 31) {
            finalize_stage(0, row0, tid, w, lane, smem, cb, x, out,
                           bel, iel, beh, ieh, bl, bh);
            int c0l = ((int*)smem)[SRI + ra];
            int c0h = ((int*)smem)[SRI + ra + 8];
            qrow_l = cb + (size_t)c0l * C_DIM;
            qrow_h = cb + (size_t)c0h * C_DIM;
        }

        if (tt + 2 < 64) copy_tile(tt + 2, buf, tid, sb);
    }

    finalize_stage(1, row0, tid, w, lane, smem, rcb, x, out,
                   bel, iel, beh, ieh, bl, bh);
}

extern "C" void kernel_launch(void* const* d_in, const int* in_sizes, int n_in,
                              void* d_out, int out_size) {
    const float* x   = (const float*)d_in[0];
    const float* cb  = (const float*)d_in[1];
    const float* rcb = (const float*)d_in[2];
    float* out = (float*)d_out;

    static int smem_set = 0;
    if (!smem_set) {
        cudaFuncSetAttribute(rq6_kernel,
                             cudaFuncAttributeMaxDynamicSharedMemorySize,
                             SMEM_FLOATS * sizeof(float));
        smem_set = 1;
    }

    prep_kernel<<<K_CODES / 256, 256>>>(cb, rcb);
    rq6_kernel<<<N_ROWS / M_TILE, THREADS, SMEM_FLOATS * sizeof(float)>>>(x, cb, rcb, out);
}